// round 15
// baseline (speedup 1.0000x reference)
#include <cuda_runtime.h>
#include <math_constants.h>

#define Bb 4
#define Pp 8192
#define Cc 64
#define Mm 2048
#define NB 64
#define OUTC 384
#define HT_STRIDE 68

// per-wg smem floats: union(hT 67*68 + h1T 128*68 = 13260; sd needs 8192) -> 13264 pad
// + sd2 64 + snn 64 + swv/swi 32  -> 13424 -> pad 13440
#define WGF 13440
// block-shared weight staging: 2 buffers x 4096 floats (16 rows x up to 256 cols)
#define WBUF_FLOATS 8192

__device__ unsigned g_progress[Bb];

// ---------------- packed f32x2 helpers (bitwise == two scalar rn ops) -------
typedef unsigned long long u64;

__device__ __forceinline__ u64 pk2(float lo, float hi) {
    u64 r; asm("mov.b64 %0, {%1, %2};" : "=l"(r) : "f"(lo), "f"(hi)); return r;
}
__device__ __forceinline__ void upk2(float& lo, float& hi, u64 v) {
    asm("mov.b64 {%0, %1}, %2;" : "=f"(lo), "=f"(hi) : "l"(v));
}
__device__ __forceinline__ u64 add2(u64 a, u64 b) {
    u64 d; asm("add.rn.f32x2 %0, %1, %2;" : "=l"(d) : "l"(a), "l"(b)); return d;
}
__device__ __forceinline__ u64 mul2(u64 a, u64 b) {
    u64 d; asm("mul.rn.f32x2 %0, %1, %2;" : "=l"(d) : "l"(a), "l"(b)); return d;
}
__device__ __forceinline__ u64 fma2(u64 a, u64 b, u64 c) {
    u64 d; asm("fma.rn.f32x2 %0, %1, %2, %3;" : "=l"(d) : "l"(a), "l"(b), "l"(c)); return d;
}
__device__ __forceinline__ unsigned ld_acq(const unsigned* p) {
    unsigned v; asm volatile("ld.acquire.gpu.global.u32 %0, [%1];" : "=r"(v) : "l"(p)); return v;
}
__device__ __forceinline__ void st_rel(unsigned* p, unsigned v) {
    asm volatile("st.release.gpu.global.u32 [%0], %1;" :: "l"(p), "r"(v) : "memory");
}
__device__ __forceinline__ void wgbar(int id) {
    asm volatile("bar.sync %0, 256;" :: "r"(id) : "memory");
}
__device__ __forceinline__ void cp_async16(unsigned dst, const float* src) {
    asm volatile("cp.async.cg.shared.global [%0], [%1], 16;" :: "r"(dst), "l"(src) : "memory");
}
__device__ __forceinline__ void cp_commit() {
    asm volatile("cp.async.commit_group;" ::: "memory");
}
template<int N>
__device__ __forceinline__ void cp_wait() {
    asm volatile("cp.async.wait_group %0;" :: "n"(N) : "memory");
}
// one-shot gather: don't pollute L1
__device__ __forceinline__ float4 ldx4(const float* p) {
    float4 v;
    asm("ld.global.nc.L1::evict_first.v4.f32 {%0,%1,%2,%3}, [%4];"
        : "=f"(v.x), "=f"(v.y), "=f"(v.z), "=f"(v.w) : "l"(p));
    return v;
}

// ---------------------------------------------------------------------------
// FPS for one batch, 512 threads (16 points/thread). Bitwise-identical
// selection to the JAX scan. Publishes progress[b] = t+1 after writing ps[t].
// ---------------------------------------------------------------------------
__device__ void fps_block(int b, const float* __restrict__ pos,
                          float* __restrict__ pos_s, unsigned* __restrict__ smu)
{
    const float* pb = pos + (size_t)b * Pp * 3;
    float* ps = pos_s + (size_t)b * Mm * 3;
    const int tid = threadIdx.x;
    const int lane = tid & 31, wrp = tid >> 5;     // 16 warps

    u64 px2[8], py2[8], pz2[8];
    unsigned mind[16];
#pragma unroll
    for (int q = 0; q < 8; q++) {
        int p0 = tid + (2 * q) * 512;
        int p1 = p0 + 512;
        px2[q] = pk2(pb[3 * p0],     pb[3 * p1]);
        py2[q] = pk2(pb[3 * p0 + 1], pb[3 * p1 + 1]);
        pz2[q] = pk2(pb[3 * p0 + 2], pb[3 * p1 + 2]);
    }
#pragma unroll
    for (int i = 0; i < 16; i++) mind[i] = __float_as_uint(1e30f);

    unsigned* swv = smu;         // [2][16]
    unsigned* swi = smu + 32;    // [2][16]

    unsigned sel = 0;
    for (int t = 0; t < Mm; t++) {
        float lx = pb[3 * sel], ly = pb[3 * sel + 1], lz = pb[3 * sel + 2];
        if (tid == 0) {
            ps[3 * t] = lx; ps[3 * t + 1] = ly; ps[3 * t + 2] = lz;
            st_rel(&g_progress[b], (unsigned)(t + 1));
        }

        u64 nx2 = pk2(-lx, -lx);
        u64 ny2 = pk2(-ly, -ly);
        u64 nz2 = pk2(-lz, -lz);

#pragma unroll
        for (int q = 0; q < 8; q++) {
            u64 dx = add2(px2[q], nx2);
            u64 dy = add2(py2[q], ny2);
            u64 dz = add2(pz2[q], nz2);
            u64 s  = add2(add2(mul2(dx, dx), mul2(dy, dy)), mul2(dz, dz));
            float dlo, dhi;
            upk2(dlo, dhi, s);
            mind[2 * q]     = min(mind[2 * q],     __float_as_uint(dlo));
            mind[2 * q + 1] = min(mind[2 * q + 1], __float_as_uint(dhi));
        }
        // 15-op max tree (d2 >= 0 -> uint order == float order)
        unsigned bv;
        {
            unsigned a0 = max(mind[0], mind[1]),  a1 = max(mind[2], mind[3]);
            unsigned a2 = max(mind[4], mind[5]),  a3 = max(mind[6], mind[7]);
            unsigned a4 = max(mind[8], mind[9]),  a5 = max(mind[10], mind[11]);
            unsigned a6 = max(mind[12], mind[13]), a7 = max(mind[14], mind[15]);
            unsigned b0 = max(a0, a1), b1 = max(a2, a3), b2 = max(a4, a5), b3 = max(a6, a7);
            bv = max(max(b0, b1), max(b2, b3));
        }

        unsigned wv = __reduce_max_sync(0xffffffffu, bv);
        unsigned cand = 0xffffffffu;
        if (bv == wv) {
#pragma unroll
            for (int i = 15; i >= 0; i--)
                if (mind[i] == wv) cand = (unsigned)(tid + (i << 9));
        }
        unsigned wi = __reduce_min_sync(0xffffffffu, cand);

        const int buf = (t & 1) * 16;
        if (lane == 0) { swv[buf + wrp] = wv; swi[buf + wrp] = wi; }
        __syncthreads();

        unsigned v  = (lane < 16) ? swv[buf + lane] : 0u;
        unsigned ii = (lane < 16) ? swi[buf + lane] : 0xffffffffu;
        unsigned gv = __reduce_max_sync(0xffffffffu, v);
        unsigned c2 = (v == gv && lane < 16) ? ii : 0xffffffffu;
        sel = __reduce_min_sync(0xffffffffu, c2);
    }
}

// ---------------------------------------------------------------------------
// per-centroid MLP branch. Weights staged through block-shared smem with
// cp.async double buffering (16-row tiles); both 256-thread wgs consume the
// same tiles in lockstep (block-wide __syncthreads per stage).
// Per-(k,channel) accumulation order over c/i identical to reference.
// ---------------------------------------------------------------------------
template<int K, int H1, int H2>
__device__ __forceinline__ void run_branch(
    const float* __restrict__ hT, float* __restrict__ h1T,
    const float* __restrict__ sd2,
    const float* __restrict__ W1, const float* __restrict__ B1b,
    const float* __restrict__ W2, const float* __restrict__ B2b,
    float* __restrict__ wbuf, unsigned wbuf_a, int tid512,
    float* __restrict__ outrow, float r2, int tx, int ty, int t)
{
    constexpr int KV = K / 8;     // neighbors per thread
    constexpr int IU = H1 / 32, IU2 = IU / 2;
    constexpr int JU = H2 / 32, JU2 = JU / 2;
    constexpr bool SPLIT = (JU == 8);

    auto stage_load = [&](const float* W, int rows, int rowlen, int s) {
        int r0 = s * 16;
        int nrow = rows - r0; if (nrow > 16) nrow = 16;
        int elems = nrow * rowlen;
        unsigned dst = wbuf_a + (unsigned)((s & 1) * (WBUF_FLOATS / 2) * 4);
        const float* src = W + r0 * rowlen;
        for (int idx = tid512 * 4; idx < elems; idx += 2048)
            cp_async16(dst + (unsigned)(idx * 4), src + idx);
        cp_commit();
    };
    auto lda = [&](float* a, const float* base) {
        const float4* hp = (const float4*)base;
#pragma unroll
        for (int q = 0; q < KV / 4; q++) {
            float4 t4 = hp[q];
            a[4*q] = t4.x; a[4*q+1] = t4.y; a[4*q+2] = t4.z; a[4*q+3] = t4.w;
        }
    };

    // ---- GEMM1: h1[i][k] = relu(sum_c hT[c][k]*W1[c][i] + b1[i]) ----
    {
        u64 acc[KV][IU2];
#pragma unroll
        for (int v = 0; v < KV; v++)
#pragma unroll
            for (int u = 0; u < IU2; u++) acc[v][u] = 0ull;

        constexpr int NST = 5;   // ceil(67/16)
        stage_load(W1, 67, H1, 0);
        for (int s = 0; s < NST; s++) {
            if (s + 1 < NST) { stage_load(W1, 67, H1, s + 1); cp_wait<1>(); }
            else             { cp_wait<0>(); }
            __syncthreads();
            const float* wb = wbuf + (s & 1) * (WBUF_FLOATS / 2);
            const int nrow = (s == NST - 1) ? 3 : 16;
            for (int r = 0; r < nrow; r++) {
                int c = s * 16 + r;
                float a[KV];
                lda(a, hT + c * HT_STRIDE + ty * KV);
                u64 bb[IU2];
                if constexpr (IU == 4) {
                    float4 w4 = *(const float4*)(wb + r * H1 + tx * 4);
                    bb[0] = pk2(w4.x, w4.y); bb[1] = pk2(w4.z, w4.w);
                } else {
                    float2 w2 = *(const float2*)(wb + r * H1 + tx * 2);
                    bb[0] = pk2(w2.x, w2.y);
                }
#pragma unroll
                for (int v = 0; v < KV; v++) {
                    u64 av = pk2(a[v], a[v]);
#pragma unroll
                    for (int u = 0; u < IU2; u++)
                        acc[v][u] = fma2(av, bb[u], acc[v][u]);
                }
            }
            __syncthreads();
        }

        float bias[IU];
#pragma unroll
        for (int u = 0; u < IU; u++) bias[u] = B1b[tx * IU + u];
#pragma unroll
        for (int u = 0; u < IU2; u++) {
#pragma unroll
            for (int v = 0; v < KV; v++) {
                float lo, hi;
                upk2(lo, hi, acc[v][u]);
                int i0 = tx * IU + 2 * u;
                int k  = ty * KV + v;
                h1T[i0 * HT_STRIDE + k]       = fmaxf(lo + bias[2*u],     0.f);
                h1T[(i0 + 1) * HT_STRIDE + k] = fmaxf(hi + bias[2*u + 1], 0.f);
            }
        }
    }
    // h1T visibility covered by the first __syncthreads inside GEMM2's stage 0

    // ---- GEMM2 + masked max over k ----
    {
        u64 acc[KV][JU2];
#pragma unroll
        for (int v = 0; v < KV; v++)
#pragma unroll
            for (int u = 0; u < JU2; u++) acc[v][u] = 0ull;

        constexpr int NST = H1 / 16;
        stage_load(W2, H1, H2, 0);
        for (int s = 0; s < NST; s++) {
            if (s + 1 < NST) { stage_load(W2, H1, H2, s + 1); cp_wait<1>(); }
            else             { cp_wait<0>(); }
            __syncthreads();
            const float* wb = wbuf + (s & 1) * (WBUF_FLOATS / 2);
#pragma unroll 4
            for (int r = 0; r < 16; r++) {
                int i = s * 16 + r;
                float a[KV];
                lda(a, h1T + i * HT_STRIDE + ty * KV);
                u64 bb[JU2];
                if constexpr (SPLIT) {
                    float4 wA = *(const float4*)(wb + r * H2 + tx * 4);
                    float4 wB = *(const float4*)(wb + r * H2 + H2 / 2 + tx * 4);
                    bb[0] = pk2(wA.x, wA.y); bb[1] = pk2(wA.z, wA.w);
                    bb[2] = pk2(wB.x, wB.y); bb[3] = pk2(wB.z, wB.w);
                } else {
                    float4 w4 = *(const float4*)(wb + r * H2 + tx * 4);
                    bb[0] = pk2(w4.x, w4.y); bb[1] = pk2(w4.z, w4.w);
                }
#pragma unroll
                for (int v = 0; v < KV; v++) {
                    u64 av = pk2(a[v], a[v]);
#pragma unroll
                    for (int u = 0; u < JU2; u++)
                        acc[v][u] = fma2(av, bb[u], acc[v][u]);
                }
            }
            __syncthreads();
        }

        // channel index for mx[u]
        auto CH = [&](int u) -> int {
            if constexpr (SPLIT) return (u < 4) ? (tx * 4 + u) : (H2 / 2 + tx * 4 + (u - 4));
            else                 return tx * 4 + u;
        };

        float b2[JU];
#pragma unroll
        for (int u = 0; u < JU; u++) b2[u] = B2b[CH(u)];
        float mx[JU];
#pragma unroll
        for (int u = 0; u < JU; u++) mx[u] = -1e30f;
#pragma unroll
        for (int v = 0; v < KV; v++) {
            bool ok = (sd2[ty * KV + v] <= r2);
#pragma unroll
            for (int u = 0; u < JU2; u++) {
                float lo, hi;
                upk2(lo, hi, acc[v][u]);
                float v0 = fmaxf(lo + b2[2*u],     0.f);
                float v1 = fmaxf(hi + b2[2*u + 1], 0.f);
                if (!ok) { v0 = -1e30f; v1 = -1e30f; }
                mx[2*u]     = fmaxf(mx[2*u],     v0);
                mx[2*u + 1] = fmaxf(mx[2*u + 1], v1);
            }
        }

        // red aliases h1T: last GEMM2 stage's trailing sync covered h1T reads
        float* red = h1T;   // 8 * H2 <= 2048 floats, fits in h1T region
#pragma unroll
        for (int u = 0; u < JU; u++) red[ty * H2 + CH(u)] = mx[u];
        __syncthreads();
        for (int j = t; j < H2; j += 256) {
            float mm = red[j];
#pragma unroll
            for (int w = 1; w < 8; w++) mm = fmaxf(mm, red[w * H2 + j]);
            outrow[j] = mm;
        }
        __syncthreads();
    }
}

// ---------------------------------------------------------------------------
// Fused kernel: blocks 0..3 = FPS; blocks 4.. = workers (2 sub-units x 256thr,
// SAME batch, adjacent centroids; shared weight staging through smem).
// ---------------------------------------------------------------------------
__global__ void __launch_bounds__(512, 1) fused_kernel(
    const float* __restrict__ x, const float* __restrict__ pos,
    const float* __restrict__ w1_0, const float* __restrict__ b1_0,
    const float* __restrict__ w1_1, const float* __restrict__ b1_1,
    const float* __restrict__ w2_0, const float* __restrict__ b2_0,
    const float* __restrict__ w2_1, const float* __restrict__ b2_1,
    float* __restrict__ out, float* __restrict__ pos_s)
{
    extern __shared__ float sm[];

    if (blockIdx.x < Bb) {
        fps_block(blockIdx.x, pos, pos_s, (unsigned*)sm);
        return;
    }

    const int w  = blockIdx.x - Bb;
    const int wg = threadIdx.x >> 8;          // 0..1
    const int t  = threadIdx.x & 255;
    const int barid = wg + 1;
    const int b  = w & 3;                     // same batch for both wgs
    const int m  = (w >> 2) * 2 + wg;         // adjacent centroids
    const int bm = b * Mm + m;
    const int lane = t & 31, w8 = t >> 5;
    const int tid512 = threadIdx.x;

    float*    base = sm + wg * WGF;
    float*    un   = base;                    // union: sd[8192] / hT+h1T[13260]
    float*    sd2s = base + 13264;            // 64
    int*      snn  = (int*)(base + 13328);    // 64
    unsigned* swv  = (unsigned*)(base + 13392);  // [2][8]
    unsigned* swi  = swv + 16;                   // [2][8]
    float*    wbuf = sm + 2 * WGF;            // block-shared staging (8192 floats)

    unsigned sm_a;
    {
        unsigned long long tmp;
        asm("cvta.to.shared.u64 %0, %1;" : "=l"(tmp) : "l"(sm));
        sm_a = (unsigned)tmp;
    }
    const unsigned wbuf_a = sm_a + 2u * WGF * 4u;

    // ---- wait for our centroid ----
    if (t == 0) {
        while (ld_acq(&g_progress[b]) <= (unsigned)m) __nanosleep(128);
    }
    wgbar(barid);

    const float cx = pos_s[bm * 3], cy = pos_s[bm * 3 + 1], cz = pos_s[bm * 3 + 2];
    const float* pb = pos + (size_t)b * Pp * 3;

    // ---- KNN: distances (packed, bitwise == scalar rn) ----
    float* sd = un;
    unsigned lv = 0x7f800000u, li = 0xffffffffu;
    {
        u64 c2x = pk2(cx, cx), c2y = pk2(cy, cy), c2z = pk2(cz, cz);
        const u64 SMASK = 0x8000000080000000ull;
#pragma unroll 4
        for (int q = 0; q < 16; q++) {
            int p0 = t + (2 * q) * 256;
            int p1 = p0 + 256;
            u64 X = pk2(pb[3 * p0],     pb[3 * p1]);
            u64 Y = pk2(pb[3 * p0 + 1], pb[3 * p1 + 1]);
            u64 Z = pk2(pb[3 * p0 + 2], pb[3 * p1 + 2]);
            u64 dx = add2(c2x, X ^ SMASK);    // cx + (-px) == cx - px (rn exact)
            u64 dy = add2(c2y, Y ^ SMASK);
            u64 dz = add2(c2z, Z ^ SMASK);
            u64 s  = add2(add2(mul2(dx, dx), mul2(dy, dy)), mul2(dz, dz));
            float dlo, dhi;
            upk2(dlo, dhi, s);
            sd[p0] = dlo; sd[p1] = dhi;
            unsigned v0 = __float_as_uint(dlo), v1 = __float_as_uint(dhi);
            if (v0 < lv) { lv = v0; li = (unsigned)p0; }
            if (v1 < lv) { lv = v1; li = (unsigned)p1; }
        }
    }
    wgbar(barid);

    // ---- KNN: 64 rounds of block argmin (value, then lowest index) ----
    for (int r = 0; r < NB; r++) {
        unsigned wv = __reduce_min_sync(0xffffffffu, lv);
        unsigned cand = (lv == wv) ? li : 0xffffffffu;
        unsigned wi = __reduce_min_sync(0xffffffffu, cand);
        const int buf = (r & 1) * 8;
        if (lane == 0) { swv[buf + w8] = wv; swi[buf + w8] = wi; }
        wgbar(barid);
        unsigned v  = (lane < 8) ? swv[buf + lane] : 0xffffffffu;
        unsigned ii = (lane < 8) ? swi[buf + lane] : 0xffffffffu;
        unsigned gv = __reduce_min_sync(0xffffffffu, v);
        unsigned c2 = (v == gv && lane < 8) ? ii : 0xffffffffu;
        unsigned gi = __reduce_min_sync(0xffffffffu, c2);
        if (t == 0) { snn[r] = (int)gi; sd2s[r] = __uint_as_float(gv); }
        unsigned ot = gi & 255u;                 // owner thread in wg
        if ((unsigned)w8 == (ot >> 5)) {         // owner warp: cooperative rescan
            if ((unsigned)t == ot) sd[gi] = CUDART_INF_F;
            __syncwarp();
            unsigned pp = ot + (unsigned)lane * 256u;
            unsigned vv = __float_as_uint(sd[pp]);
            unsigned mv = __reduce_min_sync(0xffffffffu, vv);
            unsigned mc = (vv == mv) ? pp : 0xffffffffu;
            unsigned mi = __reduce_min_sync(0xffffffffu, mc);
            if ((unsigned)t == ot) { lv = mv; li = mi; }
        }
    }
    wgbar(barid);

    // ---- gather hT (overwrites sd region; all KNN reads done) ----
    float* hT  = un;
    float* h1T = un + 67 * HT_STRIDE;
    for (int t2 = t; t2 < NB * (Cc / 4); t2 += 256) {
        int k = t2 >> 4, c4 = t2 & 15;
        float4 v4 = ldx4(x + ((size_t)(b * Pp) + snn[k]) * Cc + c4 * 4);
        int c = c4 * 4;
        hT[(c + 0) * HT_STRIDE + k] = v4.x;
        hT[(c + 1) * HT_STRIDE + k] = v4.y;
        hT[(c + 2) * HT_STRIDE + k] = v4.z;
        hT[(c + 3) * HT_STRIDE + k] = v4.w;
    }
    for (int t2 = t; t2 < NB * 3; t2 += 256) {
        int k = t2 / 3, d = t2 - 3 * k;
        float cd = (d == 0) ? cx : ((d == 1) ? cy : cz);
        hT[(64 + d) * HT_STRIDE + k] =
            __fsub_rn(pos[((size_t)(b * Pp) + snn[k]) * 3 + d], cd);
    }
    // phase-lock both sub-units from here (shared weight staging requires it)
    __syncthreads();

    const float R2A = (float)(0.2 * 0.2);
    const float R2B = (float)(0.4 * 0.4);
    const int tx = t & 31, ty = t >> 5;

    float* outrow = out + (size_t)bm * OUTC;
    // branch 2: K=64, 67->128->256, output channels [128,384)
    run_branch<64, 128, 256>(hT, h1T, sd2s, w2_0, b2_0, w2_1, b2_1,
                             wbuf, wbuf_a, tid512,
                             outrow + 128, R2B, tx, ty, t);
    // branch 1: K=32 (prefix of sorted 64-NN), 67->64->128, channels [0,128)
    run_branch<32, 64, 128>(hT, h1T, sd2s, w1_0, b1_0, w1_1, b1_1,
                            wbuf, wbuf_a, tid512,
                            outrow, R2A, tx, ty, t);
}

// ---------------------------------------------------------------------------
// launch
// ---------------------------------------------------------------------------
extern "C" void kernel_launch(void* const* d_in, const int* in_sizes, int n_in,
                              void* d_out, int out_size)
{
    const float* x    = (const float*)d_in[0];
    const float* pos  = (const float*)d_in[1];
    const float* w1_0 = (const float*)d_in[2];
    const float* b1_0 = (const float*)d_in[3];
    const float* w1_1 = (const float*)d_in[4];
    const float* b1_1 = (const float*)d_in[5];
    const float* w2_0 = (const float*)d_in[6];
    const float* b2_0 = (const float*)d_in[7];
    const float* w2_1 = (const float*)d_in[8];
    const float* b2_1 = (const float*)d_in[9];

    float* out   = (float*)d_out;
    float* pos_s = out + (size_t)Bb * Mm * OUTC;   // [out | pos_s] layout

    // reset progress counters every invocation (graph replay safe)
    void* paddr = nullptr;
    cudaGetSymbolAddress(&paddr, g_progress);
    cudaMemsetAsync(paddr, 0, sizeof(unsigned) * Bb);

    const int smem = (2 * WGF + WBUF_FLOATS) * 4;   // 140288 bytes
    cudaFuncSetAttribute(fused_kernel, cudaFuncAttributeMaxDynamicSharedMemorySize, smem);

    fused_kernel<<<Bb + 2 * Mm, 512, smem>>>(x, pos,
                                             w1_0, b1_0, w1_1, b1_1,
                                             w2_0, b2_0, w2_1, b2_1,
                                             out, pos_s);
}

// round 16
// speedup vs baseline: 1.0550x; 1.0550x over previous
#include <cuda_runtime.h>
#include <math_constants.h>

#define Bb 4
#define Pp 8192
#define Cc 64
#define Mm 2048
#define NB 64
#define OUTC 384
#define HT_STRIDE 68

// worker smem floats: union(hT 67*68 + h1T 128*68 = 13260; sd 8192) -> 13264
// + sd2 64 + snn 64 + swv 32 + swi 32 = 13456 floats = 53824 B
#define WKRF 13456

__device__ unsigned g_progress[Bb];

// ---------------- packed f32x2 helpers (bitwise == two scalar rn ops) -------
typedef unsigned long long u64;

__device__ __forceinline__ u64 pk2(float lo, float hi) {
    u64 r; asm("mov.b64 %0, {%1, %2};" : "=l"(r) : "f"(lo), "f"(hi)); return r;
}
__device__ __forceinline__ void upk2(float& lo, float& hi, u64 v) {
    asm("mov.b64 {%0, %1}, %2;" : "=f"(lo), "=f"(hi) : "l"(v));
}
__device__ __forceinline__ u64 add2(u64 a, u64 b) {
    u64 d; asm("add.rn.f32x2 %0, %1, %2;" : "=l"(d) : "l"(a), "l"(b)); return d;
}
__device__ __forceinline__ u64 mul2(u64 a, u64 b) {
    u64 d; asm("mul.rn.f32x2 %0, %1, %2;" : "=l"(d) : "l"(a), "l"(b)); return d;
}
__device__ __forceinline__ u64 fma2(u64 a, u64 b, u64 c) {
    u64 d; asm("fma.rn.f32x2 %0, %1, %2, %3;" : "=l"(d) : "l"(a), "l"(b), "l"(c)); return d;
}
__device__ __forceinline__ unsigned ld_acq(const unsigned* p) {
    unsigned v; asm volatile("ld.acquire.gpu.global.u32 %0, [%1];" : "=r"(v) : "l"(p)); return v;
}
__device__ __forceinline__ void st_rel(unsigned* p, unsigned v) {
    asm volatile("st.release.gpu.global.u32 [%0], %1;" :: "l"(p), "r"(v) : "memory");
}
// weights: keep resident in L1 across blocks on the same SM
__device__ __forceinline__ float4 ldw4(const float* p) {
    float4 v;
    asm("ld.global.nc.L1::evict_last.v4.f32 {%0,%1,%2,%3}, [%4];"
        : "=f"(v.x), "=f"(v.y), "=f"(v.z), "=f"(v.w) : "l"(p));
    return v;
}
__device__ __forceinline__ float2 ldw2(const float* p) {
    float2 v;
    asm("ld.global.nc.L1::evict_last.v2.f32 {%0,%1}, [%2];"
        : "=f"(v.x), "=f"(v.y) : "l"(p));
    return v;
}
__device__ __forceinline__ float ldw1(const float* p) {
    float v;
    asm("ld.global.nc.L1::evict_last.f32 %0, [%1];" : "=f"(v) : "l"(p));
    return v;
}
// streaming data: don't displace weights
__device__ __forceinline__ float4 ldx4(const float* p) {
    float4 v;
    asm("ld.global.nc.L1::evict_first.v4.f32 {%0,%1,%2,%3}, [%4];"
        : "=f"(v.x), "=f"(v.y), "=f"(v.z), "=f"(v.w) : "l"(p));
    return v;
}
__device__ __forceinline__ float ldx1(const float* p) {
    float v;
    asm("ld.global.nc.L1::evict_first.f32 %0, [%1];" : "=f"(v) : "l"(p));
    return v;
}

// ---------------------------------------------------------------------------
// FPS for one batch, 512 threads (16 points/thread). Bitwise-identical
// selection to the JAX scan. Publishes progress[b] = t+1 after writing ps[t].
// ---------------------------------------------------------------------------
__device__ void fps_block(int b, const float* __restrict__ pos,
                          float* __restrict__ pos_s, unsigned* __restrict__ smu)
{
    const float* pb = pos + (size_t)b * Pp * 3;
    float* ps = pos_s + (size_t)b * Mm * 3;
    const int tid = threadIdx.x;
    const int lane = tid & 31, wrp = tid >> 5;     // 16 warps

    u64 px2[8], py2[8], pz2[8];
    unsigned mind[16];
#pragma unroll
    for (int q = 0; q < 8; q++) {
        int p0 = tid + (2 * q) * 512;
        int p1 = p0 + 512;
        px2[q] = pk2(pb[3 * p0],     pb[3 * p1]);
        py2[q] = pk2(pb[3 * p0 + 1], pb[3 * p1 + 1]);
        pz2[q] = pk2(pb[3 * p0 + 2], pb[3 * p1 + 2]);
    }
#pragma unroll
    for (int i = 0; i < 16; i++) mind[i] = __float_as_uint(1e30f);

    unsigned* swv = smu;         // [2][16]
    unsigned* swi = smu + 32;    // [2][16]

    unsigned sel = 0;
    for (int t = 0; t < Mm; t++) {
        float lx = pb[3 * sel], ly = pb[3 * sel + 1], lz = pb[3 * sel + 2];
        if (tid == 0) {
            ps[3 * t] = lx; ps[3 * t + 1] = ly; ps[3 * t + 2] = lz;
            st_rel(&g_progress[b], (unsigned)(t + 1));
        }

        u64 nx2 = pk2(-lx, -lx);
        u64 ny2 = pk2(-ly, -ly);
        u64 nz2 = pk2(-lz, -lz);

#pragma unroll
        for (int q = 0; q < 8; q++) {
            u64 dx = add2(px2[q], nx2);
            u64 dy = add2(py2[q], ny2);
            u64 dz = add2(pz2[q], nz2);
            u64 s  = add2(add2(mul2(dx, dx), mul2(dy, dy)), mul2(dz, dz));
            float dlo, dhi;
            upk2(dlo, dhi, s);
            mind[2 * q]     = min(mind[2 * q],     __float_as_uint(dlo));
            mind[2 * q + 1] = min(mind[2 * q + 1], __float_as_uint(dhi));
        }
        // 15-op max tree (d2 >= 0 -> uint order == float order)
        unsigned bv;
        {
            unsigned a0 = max(mind[0], mind[1]),  a1 = max(mind[2], mind[3]);
            unsigned a2 = max(mind[4], mind[5]),  a3 = max(mind[6], mind[7]);
            unsigned a4 = max(mind[8], mind[9]),  a5 = max(mind[10], mind[11]);
            unsigned a6 = max(mind[12], mind[13]), a7 = max(mind[14], mind[15]);
            unsigned b0 = max(a0, a1), b1 = max(a2, a3), b2 = max(a4, a5), b3 = max(a6, a7);
            bv = max(max(b0, b1), max(b2, b3));
        }

        unsigned wv = __reduce_max_sync(0xffffffffu, bv);
        unsigned cand = 0xffffffffu;
        if (bv == wv) {
#pragma unroll
            for (int i = 15; i >= 0; i--)
                if (mind[i] == wv) cand = (unsigned)(tid + (i << 9));
        }
        unsigned wi = __reduce_min_sync(0xffffffffu, cand);

        const int buf = (t & 1) * 16;
        if (lane == 0) { swv[buf + wrp] = wv; swi[buf + wrp] = wi; }
        __syncthreads();

        unsigned v  = (lane < 16) ? swv[buf + lane] : 0u;
        unsigned ii = (lane < 16) ? swi[buf + lane] : 0xffffffffu;
        unsigned gv = __reduce_max_sync(0xffffffffu, v);
        unsigned c2 = (v == gv && lane < 16) ? ii : 0xffffffffu;
        sel = __reduce_min_sync(0xffffffffu, c2);
    }
}

// ---------------------------------------------------------------------------
// Branch 2 (K=64, 67->128->256), 512 threads on one centroid.
// GEMM1: warp=8i x 64k; lane=(kk 8, ii 4); thread = 8k x 2i.
// GEMM2: warp=16j x 64k; lane=(kk 8, jj 4); thread = 8k x 4j.
// Accumulation order over c/i identical to reference (bitwise).
// ---------------------------------------------------------------------------
__device__ __forceinline__ void branch2(
    const float* __restrict__ hT, float* __restrict__ h1T,
    const float* __restrict__ sd2,
    const float* __restrict__ W1, const float* __restrict__ B1b,
    const float* __restrict__ W2, const float* __restrict__ B2b,
    float* __restrict__ outrow, float r2, int t)
{
    const int wrp = t >> 5, lane = t & 31;
    const int kk = lane >> 2, q4 = lane & 3;
    const int kbase = kk * 8;

    // ---- GEMM1 ----
    {
        const int i0 = wrp * 8 + q4 * 2;
        u64 acc[8];
#pragma unroll
        for (int v = 0; v < 8; v++) acc[v] = 0ull;

        for (int c = 0; c < 67; c++) {
            const float* hp = hT + c * HT_STRIDE + kbase;
            float4 a0 = *(const float4*)hp;
            float4 a1 = *(const float4*)(hp + 4);
            float2 wv = ldw2(W1 + c * 128 + i0);
            u64 wb = pk2(wv.x, wv.y);
            float a[8] = {a0.x, a0.y, a0.z, a0.w, a1.x, a1.y, a1.z, a1.w};
#pragma unroll
            for (int v = 0; v < 8; v++)
                acc[v] = fma2(pk2(a[v], a[v]), wb, acc[v]);
        }
        float blo = B1b[i0], bhi = B1b[i0 + 1];
        float rlo[8], rhi[8];
#pragma unroll
        for (int v = 0; v < 8; v++) {
            float lo, hi;
            upk2(lo, hi, acc[v]);
            rlo[v] = fmaxf(lo + blo, 0.f);
            rhi[v] = fmaxf(hi + bhi, 0.f);
        }
        float4 s0 = {rlo[0], rlo[1], rlo[2], rlo[3]};
        float4 s1 = {rlo[4], rlo[5], rlo[6], rlo[7]};
        float4 s2 = {rhi[0], rhi[1], rhi[2], rhi[3]};
        float4 s3 = {rhi[4], rhi[5], rhi[6], rhi[7]};
        *(float4*)(h1T + i0 * HT_STRIDE + kbase)           = s0;
        *(float4*)(h1T + i0 * HT_STRIDE + kbase + 4)       = s1;
        *(float4*)(h1T + (i0 + 1) * HT_STRIDE + kbase)     = s2;
        *(float4*)(h1T + (i0 + 1) * HT_STRIDE + kbase + 4) = s3;
    }
    __syncthreads();

    // ---- GEMM2 + masked max ----
    {
        const int jbase = wrp * 16 + q4 * 4;
        u64 acc[8][2];
#pragma unroll
        for (int v = 0; v < 8; v++) { acc[v][0] = 0ull; acc[v][1] = 0ull; }

        for (int i = 0; i < 128; i++) {
            const float* hp = h1T + i * HT_STRIDE + kbase;
            float4 a0 = *(const float4*)hp;
            float4 a1 = *(const float4*)(hp + 4);
            float4 wv = ldw4(W2 + i * 256 + jbase);
            u64 wb0 = pk2(wv.x, wv.y), wb1 = pk2(wv.z, wv.w);
            float a[8] = {a0.x, a0.y, a0.z, a0.w, a1.x, a1.y, a1.z, a1.w};
#pragma unroll
            for (int v = 0; v < 8; v++) {
                u64 av = pk2(a[v], a[v]);
                acc[v][0] = fma2(av, wb0, acc[v][0]);
                acc[v][1] = fma2(av, wb1, acc[v][1]);
            }
        }

        float4 s0 = *(const float4*)(sd2 + kbase);
        float4 s1 = *(const float4*)(sd2 + kbase + 4);
        float sdk[8] = {s0.x, s0.y, s0.z, s0.w, s1.x, s1.y, s1.z, s1.w};
        float mx[4];
#pragma unroll
        for (int p = 0; p < 2; p++) {
            float blo = B2b[jbase + 2 * p], bhi = B2b[jbase + 2 * p + 1];
            float mlo = -1e30f, mhi = -1e30f;
#pragma unroll
            for (int v = 0; v < 8; v++) {
                float lo, hi;
                upk2(lo, hi, acc[v][p]);
                float vlo = fmaxf(lo + blo, 0.f);
                float vhi = fmaxf(hi + bhi, 0.f);
                if (!(sdk[v] <= r2)) { vlo = -1e30f; vhi = -1e30f; }
                mlo = fmaxf(mlo, vlo);
                mhi = fmaxf(mhi, vhi);
            }
            mx[2 * p] = mlo; mx[2 * p + 1] = mhi;
        }
        // max across kk lanes (bits 2..4); fp max exact here (no NaN)
#pragma unroll
        for (int off = 4; off <= 16; off <<= 1)
#pragma unroll
            for (int u = 0; u < 4; u++)
                mx[u] = fmaxf(mx[u], __shfl_xor_sync(0xffffffffu, mx[u], off));
        if (kk == 0) {
            float4 o = {mx[0], mx[1], mx[2], mx[3]};
            *(float4*)(outrow + jbase) = o;
        }
    }
}

// ---------------------------------------------------------------------------
// Branch 1 (K=32, 67->64->128), 512 threads.
// GEMM1: warp=4i x 32k; lane=(kk 8, ii 4); thread = 4k x 1i.
// GEMM2: warp=8j x 32k; lane=(kk 8, jj 4); thread = 4k x 2j.
// ---------------------------------------------------------------------------
__device__ __forceinline__ void branch1(
    const float* __restrict__ hT, float* __restrict__ h1T,
    const float* __restrict__ sd2,
    const float* __restrict__ W1, const float* __restrict__ B1b,
    const float* __restrict__ W2, const float* __restrict__ B2b,
    float* __restrict__ outrow, float r2, int t)
{
    const int wrp = t >> 5, lane = t & 31;
    const int kk = lane >> 2, q4 = lane & 3;
    const int kbase = kk * 4;

    // ---- GEMM1 ----
    {
        const int i0 = wrp * 4 + q4;
        float acc[4] = {0.f, 0.f, 0.f, 0.f};
        for (int c = 0; c < 67; c++) {
            float4 a4 = *(const float4*)(hT + c * HT_STRIDE + kbase);
            float wv = ldw1(W1 + c * 64 + i0);
            acc[0] = fmaf(a4.x, wv, acc[0]);
            acc[1] = fmaf(a4.y, wv, acc[1]);
            acc[2] = fmaf(a4.z, wv, acc[2]);
            acc[3] = fmaf(a4.w, wv, acc[3]);
        }
        float bias = B1b[i0];
        float4 s;
        s.x = fmaxf(acc[0] + bias, 0.f);
        s.y = fmaxf(acc[1] + bias, 0.f);
        s.z = fmaxf(acc[2] + bias, 0.f);
        s.w = fmaxf(acc[3] + bias, 0.f);
        *(float4*)(h1T + i0 * HT_STRIDE + kbase) = s;
    }
    __syncthreads();

    // ---- GEMM2 + masked max ----
    {
        const int jbase = wrp * 8 + q4 * 2;
        u64 acc[4] = {0ull, 0ull, 0ull, 0ull};
        for (int i = 0; i < 64; i++) {
            float4 a4 = *(const float4*)(h1T + i * HT_STRIDE + kbase);
            float2 wv = ldw2(W2 + i * 128 + jbase);
            u64 wb = pk2(wv.x, wv.y);
            acc[0] = fma2(pk2(a4.x, a4.x), wb, acc[0]);
            acc[1] = fma2(pk2(a4.y, a4.y), wb, acc[1]);
            acc[2] = fma2(pk2(a4.z, a4.z), wb, acc[2]);
            acc[3] = fma2(pk2(a4.w, a4.w), wb, acc[3]);
        }
        float4 sv = *(const float4*)(sd2 + kbase);
        float sdk[4] = {sv.x, sv.y, sv.z, sv.w};
        float blo = B2b[jbase], bhi = B2b[jbase + 1];
        float mlo = -1e30f, mhi = -1e30f;
#pragma unroll
        for (int v = 0; v < 4; v++) {
            float lo, hi;
            upk2(lo, hi, acc[v]);
            float vlo = fmaxf(lo + blo, 0.f);
            float vhi = fmaxf(hi + bhi, 0.f);
            if (!(sdk[v] <= r2)) { vlo = -1e30f; vhi = -1e30f; }
            mlo = fmaxf(mlo, vlo);
            mhi = fmaxf(mhi, vhi);
        }
#pragma unroll
        for (int off = 4; off <= 16; off <<= 1) {
            mlo = fmaxf(mlo, __shfl_xor_sync(0xffffffffu, mlo, off));
            mhi = fmaxf(mhi, __shfl_xor_sync(0xffffffffu, mhi, off));
        }
        if (kk == 0) {
            float2 o = {mlo, mhi};
            *(float2*)(outrow + jbase) = o;
        }
    }
}

// ---------------------------------------------------------------------------
// Fused kernel: blocks 0..3 = FPS; blocks 4.. = one centroid per 512-thread
// block (KNN + gather + both MLP branches), spin-waiting on FPS progress.
// ---------------------------------------------------------------------------
__global__ void __launch_bounds__(512, 1) fused_kernel(
    const float* __restrict__ x, const float* __restrict__ pos,
    const float* __restrict__ w1_0, const float* __restrict__ b1_0,
    const float* __restrict__ w1_1, const float* __restrict__ b1_1,
    const float* __restrict__ w2_0, const float* __restrict__ b2_0,
    const float* __restrict__ w2_1, const float* __restrict__ b2_1,
    float* __restrict__ out, float* __restrict__ pos_s)
{
    extern __shared__ float sm[];

    if (blockIdx.x < Bb) {
        fps_block(blockIdx.x, pos, pos_s, (unsigned*)sm);
        return;
    }

    const int w = blockIdx.x - Bb;
    const int b = w & 3;
    const int m = w >> 2;
    const int bm = b * Mm + m;
    const int t = threadIdx.x;
    const int lane = t & 31, wrp = t >> 5;

    float*    un   = sm;                       // union: sd[8192] / hT+h1T[13260]
    float*    sd2s = sm + 13264;               // 64
    int*      snn  = (int*)(sm + 13328);       // 64
    unsigned* swv  = (unsigned*)(sm + 13392);  // [2][16]
    unsigned* swi  = swv + 32;                 // [2][16]

    // ---- wait for our centroid ----
    if (t == 0) {
        while (ld_acq(&g_progress[b]) <= (unsigned)m) __nanosleep(128);
    }
    __syncthreads();

    const float cx = pos_s[bm * 3], cy = pos_s[bm * 3 + 1], cz = pos_s[bm * 3 + 2];
    const float* pb = pos + (size_t)b * Pp * 3;

    // ---- KNN: distances (packed, bitwise == scalar rn); 16 points/thread ----
    float* sd = un;
    unsigned lv = 0x7f800000u, li = 0xffffffffu;
    {
        u64 c2x = pk2(cx, cx), c2y = pk2(cy, cy), c2z = pk2(cz, cz);
        const u64 SMASK = 0x8000000080000000ull;
#pragma unroll
        for (int q = 0; q < 8; q++) {
            int p0 = t + (2 * q) * 512;
            int p1 = p0 + 512;
            u64 X = pk2(ldx1(pb + 3 * p0),     ldx1(pb + 3 * p1));
            u64 Y = pk2(ldx1(pb + 3 * p0 + 1), ldx1(pb + 3 * p1 + 1));
            u64 Z = pk2(ldx1(pb + 3 * p0 + 2), ldx1(pb + 3 * p1 + 2));
            u64 dx = add2(c2x, X ^ SMASK);    // cx + (-px) == cx - px (rn exact)
            u64 dy = add2(c2y, Y ^ SMASK);
            u64 dz = add2(c2z, Z ^ SMASK);
            u64 s  = add2(add2(mul2(dx, dx), mul2(dy, dy)), mul2(dz, dz));
            float dlo, dhi;
            upk2(dlo, dhi, s);
            sd[p0] = dlo; sd[p1] = dhi;
            unsigned v0 = __float_as_uint(dlo), v1 = __float_as_uint(dhi);
            if (v0 < lv) { lv = v0; li = (unsigned)p0; }
            if (v1 < lv) { lv = v1; li = (unsigned)p1; }
        }
    }
    __syncthreads();

    // ---- KNN: 64 rounds of block argmin (value, then lowest index) ----
    for (int r = 0; r < NB; r++) {
        unsigned wv = __reduce_min_sync(0xffffffffu, lv);
        unsigned cand = (lv == wv) ? li : 0xffffffffu;
        unsigned wi = __reduce_min_sync(0xffffffffu, cand);
        const int buf = (r & 1) * 16;
        if (lane == 0) { swv[buf + wrp] = wv; swi[buf + wrp] = wi; }
        __syncthreads();
        unsigned v  = (lane < 16) ? swv[buf + lane] : 0xffffffffu;
        unsigned ii = (lane < 16) ? swi[buf + lane] : 0xffffffffu;
        unsigned gv = __reduce_min_sync(0xffffffffu, v);
        unsigned c2 = (v == gv && lane < 16) ? ii : 0xffffffffu;
        unsigned gi = __reduce_min_sync(0xffffffffu, c2);
        if (t == 0) { snn[r] = (int)gi; sd2s[r] = __uint_as_float(gv); }
        unsigned ot = gi & 511u;                 // owner thread in block
        if ((unsigned)wrp == (ot >> 5)) {        // owner warp: cooperative rescan
            if ((unsigned)t == ot) sd[gi] = CUDART_INF_F;
            __syncwarp();
            unsigned vv = 0xffffffffu, pp = 0xffffffffu;
            if (lane < 16) {
                pp = ot + (unsigned)lane * 512u;
                vv = __float_as_uint(sd[pp]);
            }
            unsigned mv = __reduce_min_sync(0xffffffffu, vv);
            unsigned mc = (vv == mv) ? pp : 0xffffffffu;
            unsigned mi = __reduce_min_sync(0xffffffffu, mc);
            if ((unsigned)t == ot) { lv = mv; li = mi; }
        }
    }
    __syncthreads();

    // ---- gather hT (overwrites sd region; all KNN reads done) ----
    float* hT  = un;
    float* h1T = un + 67 * HT_STRIDE;
    for (int t2 = t; t2 < NB * (Cc / 4); t2 += 512) {
        int k = t2 >> 4, c4 = t2 & 15;
        float4 v4 = ldx4(x + ((size_t)(b * Pp) + snn[k]) * Cc + c4 * 4);
        int c = c4 * 4;
        hT[(c + 0) * HT_STRIDE + k] = v4.x;
        hT[(c + 1) * HT_STRIDE + k] = v4.y;
        hT[(c + 2) * HT_STRIDE + k] = v4.z;
        hT[(c + 3) * HT_STRIDE + k] = v4.w;
    }
    if (t < NB * 3) {
        int k = t / 3, d = t - 3 * k;
        float cd = (d == 0) ? cx : ((d == 1) ? cy : cz);
        hT[(64 + d) * HT_STRIDE + k] =
            __fsub_rn(ldx1(pos + ((size_t)(b * Pp) + snn[k]) * 3 + d), cd);
    }
    __syncthreads();

    const float R2A = (float)(0.2 * 0.2);
    const float R2B = (float)(0.4 * 0.4);

    float* outrow = out + (size_t)bm * OUTC;
    // branch 2: K=64, 67->128->256, output channels [128,384)
    branch2(hT, h1T, sd2s, w2_0, b2_0, w2_1, b2_1, outrow + 128, R2B, t);
    __syncthreads();   // branch2's h1T reads complete before branch1 overwrites
    // branch 1: K=32 (prefix of sorted 64-NN), 67->64->128, channels [0,128)
    branch1(hT, h1T, sd2s, w1_0, b1_0, w1_1, b1_1, outrow, R2A, t);
}

// ---------------------------------------------------------------------------
// launch
// ---------------------------------------------------------------------------
extern "C" void kernel_launch(void* const* d_in, const int* in_sizes, int n_in,
                              void* d_out, int out_size)
{
    const float* x    = (const float*)d_in[0];
    const float* pos  = (const float*)d_in[1];
    const float* w1_0 = (const float*)d_in[2];
    const float* b1_0 = (const float*)d_in[3];
    const float* w1_1 = (const float*)d_in[4];
    const float* b1_1 = (const float*)d_in[5];
    const float* w2_0 = (const float*)d_in[6];
    const float* b2_0 = (const float*)d_in[7];
    const float* w2_1 = (const float*)d_in[8];
    const float* b2_1 = (const float*)d_in[9];

    float* out   = (float*)d_out;
    float* pos_s = out + (size_t)Bb * Mm * OUTC;   // [out | pos_s] layout

    // reset progress counters every invocation (graph replay safe)
    void* paddr = nullptr;
    cudaGetSymbolAddress(&paddr, g_progress);
    cudaMemsetAsync(paddr, 0, sizeof(unsigned) * Bb);

    const int smem = WKRF * 4;   // 53824 bytes
    cudaFuncSetAttribute(fused_kernel, cudaFuncAttributeMaxDynamicSharedMemorySize, smem);

    fused_kernel<<<Bb + Bb * Mm, 512, smem>>>(x, pos,
                                              w1_0, b1_0, w1_1, b1_1,
                                              w2_0, b2_0, w2_1, b2_1,
                                              out, pos_s);
}

// round 17
// speedup vs baseline: 1.0612x; 1.0059x over previous
#include <cuda_runtime.h>
#include <math_constants.h>

#define Bb 4
#define Pp 8192
#define Cc 64
#define Mm 2048
#define NB 64
#define OUTC 384
#define HT_STRIDE 68

// worker smem floats: union(hT 67*68 + h1T 128*68 = 13260; sd 8192) -> 13264
// + sd2 64 + snn 64 + swv 32 + swi 32 = 13456 floats = 53824 B
#define WKRF 13456

__device__ unsigned g_progress[Bb];

// ---------------- packed f32x2 helpers (bitwise == two scalar rn ops) -------
typedef unsigned long long u64;

__device__ __forceinline__ u64 pk2(float lo, float hi) {
    u64 r; asm("mov.b64 %0, {%1, %2};" : "=l"(r) : "f"(lo), "f"(hi)); return r;
}
__device__ __forceinline__ void upk2(float& lo, float& hi, u64 v) {
    asm("mov.b64 {%0, %1}, %2;" : "=f"(lo), "=f"(hi) : "l"(v));
}
__device__ __forceinline__ u64 add2(u64 a, u64 b) {
    u64 d; asm("add.rn.f32x2 %0, %1, %2;" : "=l"(d) : "l"(a), "l"(b)); return d;
}
__device__ __forceinline__ u64 mul2(u64 a, u64 b) {
    u64 d; asm("mul.rn.f32x2 %0, %1, %2;" : "=l"(d) : "l"(a), "l"(b)); return d;
}
__device__ __forceinline__ u64 fma2(u64 a, u64 b, u64 c) {
    u64 d; asm("fma.rn.f32x2 %0, %1, %2, %3;" : "=l"(d) : "l"(a), "l"(b), "l"(c)); return d;
}
__device__ __forceinline__ unsigned ld_acq(const unsigned* p) {
    unsigned v; asm volatile("ld.acquire.gpu.global.u32 %0, [%1];" : "=r"(v) : "l"(p)); return v;
}
__device__ __forceinline__ void st_rel(unsigned* p, unsigned v) {
    asm volatile("st.release.gpu.global.u32 [%0], %1;" :: "l"(p), "r"(v) : "memory");
}
__device__ __forceinline__ void wgbar(int id) {
    asm volatile("bar.sync %0, 256;" :: "r"(id) : "memory");
}
// weights: keep resident in L1 across blocks on the same SM
__device__ __forceinline__ float4 ldw4(const float* p) {
    float4 v;
    asm("ld.global.nc.L1::evict_last.v4.f32 {%0,%1,%2,%3}, [%4];"
        : "=f"(v.x), "=f"(v.y), "=f"(v.z), "=f"(v.w) : "l"(p));
    return v;
}
__device__ __forceinline__ float2 ldw2(const float* p) {
    float2 v;
    asm("ld.global.nc.L1::evict_last.v2.f32 {%0,%1}, [%2];"
        : "=f"(v.x), "=f"(v.y) : "l"(p));
    return v;
}
__device__ __forceinline__ float ldw1(const float* p) {
    float v;
    asm("ld.global.nc.L1::evict_last.f32 %0, [%1];" : "=f"(v) : "l"(p));
    return v;
}
// streaming data: don't displace weights
__device__ __forceinline__ float4 ldx4(const float* p) {
    float4 v;
    asm("ld.global.nc.L1::evict_first.v4.f32 {%0,%1,%2,%3}, [%4];"
        : "=f"(v.x), "=f"(v.y), "=f"(v.z), "=f"(v.w) : "l"(p));
    return v;
}

// ---------------------------------------------------------------------------
// FPS for one batch, 512 threads (16 points/thread). Bitwise-identical
// selection to the JAX scan. Publishes progress[b] = t+1 after writing ps[t].
// ---------------------------------------------------------------------------
__device__ void fps_block(int b, const float* __restrict__ pos,
                          float* __restrict__ pos_s, unsigned* __restrict__ smu)
{
    const float* pb = pos + (size_t)b * Pp * 3;
    float* ps = pos_s + (size_t)b * Mm * 3;
    const int tid = threadIdx.x;
    const int lane = tid & 31, wrp = tid >> 5;     // 16 warps

    u64 px2[8], py2[8], pz2[8];
    unsigned mind[16];
#pragma unroll
    for (int q = 0; q < 8; q++) {
        int p0 = tid + (2 * q) * 512;
        int p1 = p0 + 512;
        px2[q] = pk2(pb[3 * p0],     pb[3 * p1]);
        py2[q] = pk2(pb[3 * p0 + 1], pb[3 * p1 + 1]);
        pz2[q] = pk2(pb[3 * p0 + 2], pb[3 * p1 + 2]);
    }
#pragma unroll
    for (int i = 0; i < 16; i++) mind[i] = __float_as_uint(1e30f);

    unsigned* swv = smu;         // [2][16]
    unsigned* swi = smu + 32;    // [2][16]

    unsigned sel = 0;
    for (int t = 0; t < Mm; t++) {
        float lx = pb[3 * sel], ly = pb[3 * sel + 1], lz = pb[3 * sel + 2];
        if (tid == 0) {
            ps[3 * t] = lx; ps[3 * t + 1] = ly; ps[3 * t + 2] = lz;
            st_rel(&g_progress[b], (unsigned)(t + 1));
        }

        u64 nx2 = pk2(-lx, -lx);
        u64 ny2 = pk2(-ly, -ly);
        u64 nz2 = pk2(-lz, -lz);

#pragma unroll
        for (int q = 0; q < 8; q++) {
            u64 dx = add2(px2[q], nx2);
            u64 dy = add2(py2[q], ny2);
            u64 dz = add2(pz2[q], nz2);
            u64 s  = add2(add2(mul2(dx, dx), mul2(dy, dy)), mul2(dz, dz));
            float dlo, dhi;
            upk2(dlo, dhi, s);
            mind[2 * q]     = min(mind[2 * q],     __float_as_uint(dlo));
            mind[2 * q + 1] = min(mind[2 * q + 1], __float_as_uint(dhi));
        }
        // 15-op max tree (d2 >= 0 -> uint order == float order)
        unsigned bv;
        {
            unsigned a0 = max(mind[0], mind[1]),  a1 = max(mind[2], mind[3]);
            unsigned a2 = max(mind[4], mind[5]),  a3 = max(mind[6], mind[7]);
            unsigned a4 = max(mind[8], mind[9]),  a5 = max(mind[10], mind[11]);
            unsigned a6 = max(mind[12], mind[13]), a7 = max(mind[14], mind[15]);
            unsigned b0 = max(a0, a1), b1 = max(a2, a3), b2 = max(a4, a5), b3 = max(a6, a7);
            bv = max(max(b0, b1), max(b2, b3));
        }

        unsigned wv = __reduce_max_sync(0xffffffffu, bv);
        unsigned cand = 0xffffffffu;
        if (bv == wv) {
#pragma unroll
            for (int i = 15; i >= 0; i--)
                if (mind[i] == wv) cand = (unsigned)(tid + (i << 9));
        }
        unsigned wi = __reduce_min_sync(0xffffffffu, cand);

        const int buf = (t & 1) * 16;
        if (lane == 0) { swv[buf + wrp] = wv; swi[buf + wrp] = wi; }
        __syncthreads();

        unsigned v  = (lane < 16) ? swv[buf + lane] : 0u;
        unsigned ii = (lane < 16) ? swi[buf + lane] : 0xffffffffu;
        unsigned gv = __reduce_max_sync(0xffffffffu, v);
        unsigned c2 = (v == gv && lane < 16) ? ii : 0xffffffffu;
        sel = __reduce_min_sync(0xffffffffu, c2);
    }
}

// ---------------------------------------------------------------------------
// Branch 2 (K=64, 67->128->256), 512 threads on one centroid.
// GEMM1: warp=8i x 64k; lane=(kk 8, ii 4); thread = 8k x 2i.
// GEMM2: warp=16j x 64k; lane=(kk 8, jj 4); thread = 8k x 4j.
// Accumulation order over c/i identical to reference (bitwise).
// ---------------------------------------------------------------------------
__device__ __forceinline__ void branch2(
    const float* __restrict__ hT, float* __restrict__ h1T,
    const float* __restrict__ sd2,
    const float* __restrict__ W1, const float* __restrict__ B1b,
    const float* __restrict__ W2, const float* __restrict__ B2b,
    float* __restrict__ outrow, float r2, int t)
{
    const int wrp = t >> 5, lane = t & 31;
    const int kk = lane >> 2, q4 = lane & 3;
    const int kbase = kk * 8;

    // ---- GEMM1 ----
    {
        const int i0 = wrp * 8 + q4 * 2;
        u64 acc[8];
#pragma unroll
        for (int v = 0; v < 8; v++) acc[v] = 0ull;

        for (int c = 0; c < 67; c++) {
            const float* hp = hT + c * HT_STRIDE + kbase;
            float4 a0 = *(const float4*)hp;
            float4 a1 = *(const float4*)(hp + 4);
            float2 wv = ldw2(W1 + c * 128 + i0);
            u64 wb = pk2(wv.x, wv.y);
            float a[8] = {a0.x, a0.y, a0.z, a0.w, a1.x, a1.y, a1.z, a1.w};
#pragma unroll
            for (int v = 0; v < 8; v++)
                acc[v] = fma2(pk2(a[v], a[v]), wb, acc[v]);
        }
        float blo = B1b[i0], bhi = B1b[i0 + 1];
        float rlo[8], rhi[8];
#pragma unroll
        for (int v = 0; v < 8; v++) {
            float lo, hi;
            upk2(lo, hi, acc[v]);
            rlo[v] = fmaxf(lo + blo, 0.f);
            rhi[v] = fmaxf(hi + bhi, 0.f);
        }
        float4 s0 = {rlo[0], rlo[1], rlo[2], rlo[3]};
        float4 s1 = {rlo[4], rlo[5], rlo[6], rlo[7]};
        float4 s2 = {rhi[0], rhi[1], rhi[2], rhi[3]};
        float4 s3 = {rhi[4], rhi[5], rhi[6], rhi[7]};
        *(float4*)(h1T + i0 * HT_STRIDE + kbase)           = s0;
        *(float4*)(h1T + i0 * HT_STRIDE + kbase + 4)       = s1;
        *(float4*)(h1T + (i0 + 1) * HT_STRIDE + kbase)     = s2;
        *(float4*)(h1T + (i0 + 1) * HT_STRIDE + kbase + 4) = s3;
    }
    __syncthreads();

    // ---- GEMM2 + masked max ----
    {
        const int jbase = wrp * 16 + q4 * 4;
        u64 acc[8][2];
#pragma unroll
        for (int v = 0; v < 8; v++) { acc[v][0] = 0ull; acc[v][1] = 0ull; }

        for (int i = 0; i < 128; i++) {
            const float* hp = h1T + i * HT_STRIDE + kbase;
            float4 a0 = *(const float4*)hp;
            float4 a1 = *(const float4*)(hp + 4);
            float4 wv = ldw4(W2 + i * 256 + jbase);
            u64 wb0 = pk2(wv.x, wv.y), wb1 = pk2(wv.z, wv.w);
            float a[8] = {a0.x, a0.y, a0.z, a0.w, a1.x, a1.y, a1.z, a1.w};
#pragma unroll
            for (int v = 0; v < 8; v++) {
                u64 av = pk2(a[v], a[v]);
                acc[v][0] = fma2(av, wb0, acc[v][0]);
                acc[v][1] = fma2(av, wb1, acc[v][1]);
            }
        }

        float4 s0 = *(const float4*)(sd2 + kbase);
        float4 s1 = *(const float4*)(sd2 + kbase + 4);
        float sdk[8] = {s0.x, s0.y, s0.z, s0.w, s1.x, s1.y, s1.z, s1.w};
        float mx[4];
#pragma unroll
        for (int p = 0; p < 2; p++) {
            float blo = B2b[jbase + 2 * p], bhi = B2b[jbase + 2 * p + 1];
            float mlo = -1e30f, mhi = -1e30f;
#pragma unroll
            for (int v = 0; v < 8; v++) {
                float lo, hi;
                upk2(lo, hi, acc[v][p]);
                float vlo = fmaxf(lo + blo, 0.f);
                float vhi = fmaxf(hi + bhi, 0.f);
                if (!(sdk[v] <= r2)) { vlo = -1e30f; vhi = -1e30f; }
                mlo = fmaxf(mlo, vlo);
                mhi = fmaxf(mhi, vhi);
            }
            mx[2 * p] = mlo; mx[2 * p + 1] = mhi;
        }
        // max across kk lanes (bits 2..4); fp max exact here (no NaN)
#pragma unroll
        for (int off = 4; off <= 16; off <<= 1)
#pragma unroll
            for (int u = 0; u < 4; u++)
                mx[u] = fmaxf(mx[u], __shfl_xor_sync(0xffffffffu, mx[u], off));
        if (kk == 0) {
            float4 o = {mx[0], mx[1], mx[2], mx[3]};
            *(float4*)(outrow + jbase) = o;
        }
    }
}

// ---------------------------------------------------------------------------
// Branch 1 (K=32, 67->64->128), 512 threads.
// GEMM1: warp=4i x 32k; lane=(kk 8, ii 4); thread = 4k x 1i.
// GEMM2: warp=8j x 32k; lane=(kk 8, jj 4); thread = 4k x 2j.
// ---------------------------------------------------------------------------
__device__ __forceinline__ void branch1(
    const float* __restrict__ hT, float* __restrict__ h1T,
    const float* __restrict__ sd2,
    const float* __restrict__ W1, const float* __restrict__ B1b,
    const float* __restrict__ W2, const float* __restrict__ B2b,
    float* __restrict__ outrow, float r2, int t)
{
    const int wrp = t >> 5, lane = t & 31;
    const int kk = lane >> 2, q4 = lane & 3;
    const int kbase = kk * 4;

    // ---- GEMM1 ----
    {
        const int i0 = wrp * 4 + q4;
        float acc[4] = {0.f, 0.f, 0.f, 0.f};
        for (int c = 0; c < 67; c++) {
            float4 a4 = *(const float4*)(hT + c * HT_STRIDE + kbase);
            float wv = ldw1(W1 + c * 64 + i0);
            acc[0] = fmaf(a4.x, wv, acc[0]);
            acc[1] = fmaf(a4.y, wv, acc[1]);
            acc[2] = fmaf(a4.z, wv, acc[2]);
            acc[3] = fmaf(a4.w, wv, acc[3]);
        }
        float bias = B1b[i0];
        float4 s;
        s.x = fmaxf(acc[0] + bias, 0.f);
        s.y = fmaxf(acc[1] + bias, 0.f);
        s.z = fmaxf(acc[2] + bias, 0.f);
        s.w = fmaxf(acc[3] + bias, 0.f);
        *(float4*)(h1T + i0 * HT_STRIDE + kbase) = s;
    }
    __syncthreads();

    // ---- GEMM2 + masked max ----
    {
        const int jbase = wrp * 8 + q4 * 2;
        u64 acc[4] = {0ull, 0ull, 0ull, 0ull};
        for (int i = 0; i < 64; i++) {
            float4 a4 = *(const float4*)(h1T + i * HT_STRIDE + kbase);
            float2 wv = ldw2(W2 + i * 128 + jbase);
            u64 wb = pk2(wv.x, wv.y);
            acc[0] = fma2(pk2(a4.x, a4.x), wb, acc[0]);
            acc[1] = fma2(pk2(a4.y, a4.y), wb, acc[1]);
            acc[2] = fma2(pk2(a4.z, a4.z), wb, acc[2]);
            acc[3] = fma2(pk2(a4.w, a4.w), wb, acc[3]);
        }
        float4 sv = *(const float4*)(sd2 + kbase);
        float sdk[4] = {sv.x, sv.y, sv.z, sv.w};
        float blo = B2b[jbase], bhi = B2b[jbase + 1];
        float mlo = -1e30f, mhi = -1e30f;
#pragma unroll
        for (int v = 0; v < 4; v++) {
            float lo, hi;
            upk2(lo, hi, acc[v]);
            float vlo = fmaxf(lo + blo, 0.f);
            float vhi = fmaxf(hi + bhi, 0.f);
            if (!(sdk[v] <= r2)) { vlo = -1e30f; vhi = -1e30f; }
            mlo = fmaxf(mlo, vlo);
            mhi = fmaxf(mhi, vhi);
        }
#pragma unroll
        for (int off = 4; off <= 16; off <<= 1) {
            mlo = fmaxf(mlo, __shfl_xor_sync(0xffffffffu, mlo, off));
            mhi = fmaxf(mhi, __shfl_xor_sync(0xffffffffu, mhi, off));
        }
        if (kk == 0) {
            float2 o = {mlo, mhi};
            *(float2*)(outrow + jbase) = o;
        }
    }
}

// ---------------------------------------------------------------------------
// Fused kernel: blocks 0..3 = FPS; blocks 4.. = one centroid per 512-thread
// block. KNN runs on threads 0..255 only (proven 256-thread form); gather and
// MLP use all 512 threads.
// ---------------------------------------------------------------------------
__global__ void __launch_bounds__(512, 1) fused_kernel(
    const float* __restrict__ x, const float* __restrict__ pos,
    const float* __restrict__ w1_0, const float* __restrict__ b1_0,
    const float* __restrict__ w1_1, const float* __restrict__ b1_1,
    const float* __restrict__ w2_0, const float* __restrict__ b2_0,
    const float* __restrict__ w2_1, const float* __restrict__ b2_1,
    float* __restrict__ out, float* __restrict__ pos_s)
{
    extern __shared__ float sm[];

    if (blockIdx.x < Bb) {
        fps_block(blockIdx.x, pos, pos_s, (unsigned*)sm);
        return;
    }

    const int w = blockIdx.x - Bb;
    const int b = w & 3;
    const int m = w >> 2;
    const int bm = b * Mm + m;
    const int t = threadIdx.x;

    float*    un   = sm;                       // union: sd[8192] / hT+h1T[13260]
    float*    sd2s = sm + 13264;               // 64
    int*      snn  = (int*)(sm + 13328);       // 64
    unsigned* swv  = (unsigned*)(sm + 13392);  // [2][8]
    unsigned* swi  = swv + 16;                 // [2][8]

    // ---- wait for our centroid ----
    if (t == 0) {
        while (ld_acq(&g_progress[b]) <= (unsigned)m) __nanosleep(128);
    }
    __syncthreads();

    const float cx = pos_s[bm * 3], cy = pos_s[bm * 3 + 1], cz = pos_s[bm * 3 + 2];
    const float* pb = pos + (size_t)b * Pp * 3;
    float* sd = un;

    // ---- KNN on threads 0..255 (proven 256-thread form, named barrier 1) ----
    if (t < 256) {
        const int lane = t & 31, w8 = t >> 5;
        unsigned lv = 0x7f800000u, li = 0xffffffffu;
        {
            u64 c2x = pk2(cx, cx), c2y = pk2(cy, cy), c2z = pk2(cz, cz);
            const u64 SMASK = 0x8000000080000000ull;
#pragma unroll 4
            for (int q = 0; q < 16; q++) {
                int p0 = t + (2 * q) * 256;
                int p1 = p0 + 256;
                u64 X = pk2(pb[3 * p0],     pb[3 * p1]);
                u64 Y = pk2(pb[3 * p0 + 1], pb[3 * p1 + 1]);
                u64 Z = pk2(pb[3 * p0 + 2], pb[3 * p1 + 2]);
                u64 dx = add2(c2x, X ^ SMASK);   // cx + (-px) == cx - px (rn exact)
                u64 dy = add2(c2y, Y ^ SMASK);
                u64 dz = add2(c2z, Z ^ SMASK);
                u64 s  = add2(add2(mul2(dx, dx), mul2(dy, dy)), mul2(dz, dz));
                float dlo, dhi;
                upk2(dlo, dhi, s);
                sd[p0] = dlo; sd[p1] = dhi;
                unsigned v0 = __float_as_uint(dlo), v1 = __float_as_uint(dhi);
                if (v0 < lv) { lv = v0; li = (unsigned)p0; }
                if (v1 < lv) { lv = v1; li = (unsigned)p1; }
            }
        }
        wgbar(1);

        for (int r = 0; r < NB; r++) {
            unsigned wv = __reduce_min_sync(0xffffffffu, lv);
            unsigned cand = (lv == wv) ? li : 0xffffffffu;
            unsigned wi = __reduce_min_sync(0xffffffffu, cand);
            const int buf = (r & 1) * 8;
            if (lane == 0) { swv[buf + w8] = wv; swi[buf + w8] = wi; }
            wgbar(1);
            unsigned v  = (lane < 8) ? swv[buf + lane] : 0xffffffffu;
            unsigned ii = (lane < 8) ? swi[buf + lane] : 0xffffffffu;
            unsigned gv = __reduce_min_sync(0xffffffffu, v);
            unsigned c2 = (v == gv && lane < 8) ? ii : 0xffffffffu;
            unsigned gi = __reduce_min_sync(0xffffffffu, c2);
            if (t == 0) { snn[r] = (int)gi; sd2s[r] = __uint_as_float(gv); }
            unsigned ot = gi & 255u;                // owner thread (0..255)
            if ((unsigned)w8 == (ot >> 5)) {        // owner warp: cooperative rescan
                if ((unsigned)t == ot) sd[gi] = CUDART_INF_F;
                __syncwarp();
                unsigned pp = ot + (unsigned)lane * 256u;
                unsigned vv = __float_as_uint(sd[pp]);
                unsigned mv = __reduce_min_sync(0xffffffffu, vv);
                unsigned mc = (vv == mv) ? pp : 0xffffffffu;
                unsigned mi = __reduce_min_sync(0xffffffffu, mc);
                if ((unsigned)t == ot) { lv = mv; li = mi; }
            }
        }
    }
    __syncthreads();   // threads 256..511 waited here during KNN

    // ---- gather hT (overwrites sd region; all KNN reads done), 512 threads ----
    float* hT  = un;
    float* h1T = un + 67 * HT_STRIDE;
    for (int t2 = t; t2 < NB * (Cc / 4); t2 += 512) {
        int k = t2 >> 4, c4 = t2 & 15;
        float4 v4 = ldx4(x + ((size_t)(b * Pp) + snn[k]) * Cc + c4 * 4);
        int c = c4 * 4;
        hT[(c + 0) * HT_STRIDE + k] = v4.x;
        hT[(c + 1) * HT_STRIDE + k] = v4.y;
        hT[(c + 2) * HT_STRIDE + k] = v4.z;
        hT[(c + 3) * HT_STRIDE + k] = v4.w;
    }
    if (t < NB * 3) {
        int k = t / 3, d = t - 3 * k;
        float cd = (d == 0) ? cx : ((d == 1) ? cy : cz);
        hT[(64 + d) * HT_STRIDE + k] =
            __fsub_rn(pos[((size_t)(b * Pp) + snn[k]) * 3 + d], cd);
    }
    __syncthreads();

    const float R2A = (float)(0.2 * 0.2);
    const float R2B = (float)(0.4 * 0.4);

    float* outrow = out + (size_t)bm * OUTC;
    // branch 2: K=64, 67->128->256, output channels [128,384)
    branch2(hT, h1T, sd2s, w2_0, b2_0, w2_1, b2_1, outrow + 128, R2B, t);
    __syncthreads();   // branch2's h1T reads complete before branch1 overwrites
    // branch 1: K=32 (prefix of sorted 64-NN), 67->64->128, channels [0,128)
    branch1(hT, h1T, sd2s, w1_0, b1_0, w1_1, b1_1, outrow, R2A, t);
}

// ---------------------------------------------------------------------------
// launch
// ---------------------------------------------------------------------------
extern "C" void kernel_launch(void* const* d_in, const int* in_sizes, int n_in,
                              void* d_out, int out_size)
{
    const float* x    = (const float*)d_in[0];
    const float* pos  = (const float*)d_in[1];
    const float* w1_0 = (const float*)d_in[2];
    const float* b1_0 = (const float*)d_in[3];
    const float* w1_1 = (const float*)d_in[4];
    const float* b1_1 = (const float*)d_in[5];
    const float* w2_0 = (const float*)d_in[6];
    const float* b2_0 = (const float*)d_in[7];
    const float* w2_1 = (const float*)d_in[8];
    const float* b2_1 = (const float*)d_in[9];

    float* out   = (float*)d_out;
    float* pos_s = out + (size_t)Bb * Mm * OUTC;   // [out | pos_s] layout

    // reset progress counters every invocation (graph replay safe)
    void* paddr = nullptr;
    cudaGetSymbolAddress(&paddr, g_progress);
    cudaMemsetAsync(paddr, 0, sizeof(unsigned) * Bb);

    const int smem = WKRF * 4;   // 53824 bytes
    cudaFuncSetAttribute(fused_kernel, cudaFuncAttributeMaxDynamicSharedMemorySize, smem);

    fused_kernel<<<Bb + Bb * Mm, 512, smem>>>(x, pos,
                                              w1_0, b1_0, w1_1, b1_1,
                                              w2_0, b2_0, w2_1, b2_1,
                                              out, pos_s);
}